// round 14
// baseline (speedup 1.0000x reference)
#include <cuda_runtime.h>
#include <cuda_bf16.h>
#include <math.h>
#include <stdint.h>

#define B    8
#define NTOK 2048
#define FIN  256
#define D    128
#define ALPHA 0.2f
#define CHUNK  16
#define NCHUNK (NTOK/CHUNK)   // 128

// ---------------- scratch (__device__ globals) --------------------------------
__device__ float d_Wh[B*NTOK*D];
__device__ float d_s1[B*NTOK];
__device__ float d_s2[B*NTOK];
__device__ float d_ss1[B*NTOK];
__device__ float d_pe[B*NTOK];
__device__ float d_pa[B*NTOK];
__device__ float d_s2s[B*NTOK];
__device__ int   d_perm[B*NTOK];
__device__ float d_g1[B*NTOK];
__device__ float d_g2[B*NTOK];
__device__ int   d_tq[B*NTOK];
__device__ float d_e1[B*NTOK];
__device__ float d_e2[B*NTOK];
__device__ float d_loc12[B*NTOK*D*2];
__device__ float d_ct1[B*NCHUNK*D];
__device__ float d_ct2[B*NCHUNK*D];
__device__ float d_cp12[B*NCHUNK*D*2];
__device__ float d_tot1[B*D];
__device__ __nv_bfloat16 d_Wt_hi[D*FIN];
__device__ __nv_bfloat16 d_Wt_lo[D*FIN];
__device__ float d_u1[FIN];
__device__ float d_u2[FIN];

// ================= mma.sync helpers ============================================
__device__ __forceinline__ uint32_t smem_u32(const void* p) {
    uint32_t a;
    asm("{ .reg .u64 t; cvta.to.shared.u64 t, %1; cvt.u32.u64 %0, t; }" : "=r"(a) : "l"(p));
    return a;
}
__device__ __forceinline__ void ldm_x4(uint32_t& r0, uint32_t& r1, uint32_t& r2, uint32_t& r3, uint32_t addr) {
    asm volatile("ldmatrix.sync.aligned.m8n8.x4.shared.b16 {%0,%1,%2,%3}, [%4];"
        : "=r"(r0), "=r"(r1), "=r"(r2), "=r"(r3) : "r"(addr));
}
__device__ __forceinline__ void mma_bf16(float* c, const uint32_t* a, uint32_t b0, uint32_t b1) {
    asm volatile("mma.sync.aligned.m16n8k16.row.col.f32.bf16.bf16.f32 "
        "{%0,%1,%2,%3},{%4,%5,%6,%7},{%8,%9},{%0,%1,%2,%3};"
        : "+f"(c[0]), "+f"(c[1]), "+f"(c[2]), "+f"(c[3])
        : "r"(a[0]), "r"(a[1]), "r"(a[2]), "r"(a[3]), "r"(b0), "r"(b1));
}

// smem layout (bytes). Rows padded to 72 bf16 (144 B).
#define KT      64
#define ROWB    144
#define AH_OFF  0
#define AL_OFF  9216
#define BH_OFF  18432
#define BL_OFF  36864
#define SM_TOT  55296

// ---------------- K0: wconv (blocks 0..127) + u = W@a (block 128) --------------
__global__ void __launch_bounds__(256) k_u(const float* __restrict__ W,
                                           const float* __restrict__ a)
{
    if (blockIdx.x < 128) {
        int idx = blockIdx.x * 256 + threadIdx.x;
        int k = idx & 255;
        int n = idx >> 8;
        float x = W[(size_t)k * D + n];
        __nv_bfloat16 hi = __float2bfloat16_rn(x);
        __nv_bfloat16 lo = __float2bfloat16_rn(x - __bfloat162float(hi));
        d_Wt_hi[n * FIN + k] = hi;
        d_Wt_lo[n * FIN + k] = lo;
    } else {
        int k = threadIdx.x;                     // 0..255
        const float4* Wr = (const float4*)&W[(size_t)k * D];
        float u1 = 0.f, u2 = 0.f;
        #pragma unroll
        for (int n4 = 0; n4 < 32; n4++) {
            float4 w  = Wr[n4];
            float4 A1 = *(const float4*)&a[n4 * 4];
            float4 A2 = *(const float4*)&a[128 + n4 * 4];
            u1 += w.x * A1.x + w.y * A1.y + w.z * A1.z + w.w * A1.w;
            u2 += w.x * A2.x + w.y * A2.y + w.z * A2.z + w.w * A2.w;
        }
        d_u1[k] = u1;
        d_u2[k] = u2;
    }
}

// ---------------- K0b: s1 = h@u1, s2 = h@u2 (warp per row) ---------------------
__global__ void __launch_bounds__(256) k_su(const float* __restrict__ h)
{
    __shared__ float su1[FIN], su2[FIN];
    const int tid = threadIdx.x;
    su1[tid] = d_u1[tid];
    su2[tid] = d_u2[tid];
    __syncthreads();

    const int warp = tid >> 5, lane = tid & 31;
    const int row = blockIdx.x * 8 + warp;
    const float* hr = &h[(size_t)row * FIN];

    float p1 = 0.f, p2 = 0.f;
    #pragma unroll
    for (int c = 0; c < 2; c++) {
        int o = c * 128 + lane * 4;
        float4 v = *(const float4*)&hr[o];
        p1 += v.x * su1[o] + v.y * su1[o + 1] + v.z * su1[o + 2] + v.w * su1[o + 3];
        p2 += v.x * su2[o] + v.y * su2[o + 1] + v.z * su2[o + 2] + v.w * su2[o + 3];
    }
    #pragma unroll
    for (int o = 16; o > 0; o >>= 1) {
        p1 += __shfl_xor_sync(0xffffffffu, p1, o);
        p2 += __shfl_xor_sync(0xffffffffu, p2, o);
    }
    if (lane == 0) { d_s1[row] = p1; d_s2[row] = p2; }
}

// ================= 256-thread / 8-elem bitonic sort helpers ====================
__device__ __forceinline__ void cmpswap(float& ka, int& xa, float& kb, int& xb, bool up) {
    if ((ka > kb) == up) {
        float tk = ka; ka = kb; kb = tk;
        int   tx = xa; xa = xb; xb = tx;
    }
}
__device__ __forceinline__ void shuffle_pass(float* key, int* idx, int m, bool up) {
    const bool lo = ((threadIdx.x & m) == 0);
    #pragma unroll
    for (int e = 0; e < 8; e++) {
        float pk = __shfl_xor_sync(0xffffffffu, key[e], m);
        int   px = __shfl_xor_sync(0xffffffffu, idx[e], m);
        float lk = lo ? key[e] : pk;
        float hk = lo ? pk : key[e];
        if ((lk > hk) == up) { key[e] = pk; idx[e] = px; }
    }
}
__device__ __forceinline__ void tail_pass(float* key, int* idx, bool up) {
    #pragma unroll
    for (int j = 4; j >= 1; j >>= 1)
        #pragma unroll
        for (int e = 0; e < 8; e++)
            if ((e & j) == 0) cmpswap(key[e], idx[e], key[e + j], idx[e + j], up);
}

// ---------------- K1: mega — gemm (blocks 0..255) + sort (256..271) ------------
__global__ void __launch_bounds__(256, 2)
k_mega(const float* __restrict__ h)
{
    extern __shared__ char smem[];
    const int tid  = threadIdx.x;

    if (blockIdx.x < 256) {
        // ===================== GEMM: Wh = h @ W (bf16x3) =======================
        const uint32_t sb = smem_u32(smem);
        const int wid  = tid >> 5;
        const int lane = tid & 31;
        const int rowBase = blockIdx.x * 64;

        const int mb0 = (wid & 3) * 16;
        const int nbh = wid >> 2;
        const int nb  = nbh * 64;

        float acc[8][4] = {};

        for (int t = 0; t < 4; t++) {
            const int kt = t * KT;
            __syncthreads();

            #pragma unroll
            for (int l = 0; l < 4; l++) {
                int f4 = tid + l * 256;
                int r  = f4 >> 4;
                int c  = (f4 & 15) * 4;
                float4 v = *(const float4*)&h[(size_t)(rowBase + r) * FIN + kt + c];
                __nv_bfloat162 h0 = __floats2bfloat162_rn(v.x, v.y);
                __nv_bfloat162 h1 = __floats2bfloat162_rn(v.z, v.w);
                __nv_bfloat162 l0 = __floats2bfloat162_rn(v.x - __bfloat162float(h0.x),
                                                          v.y - __bfloat162float(h0.y));
                __nv_bfloat162 l1 = __floats2bfloat162_rn(v.z - __bfloat162float(h1.x),
                                                          v.w - __bfloat162float(h1.y));
                uint32_t off = (uint32_t)r * ROWB + (uint32_t)c * 2;
                *(uint2*)(smem + AH_OFF + off) = make_uint2(*(uint32_t*)&h0, *(uint32_t*)&h1);
                *(uint2*)(smem + AL_OFF + off) = make_uint2(*(uint32_t*)&l0, *(uint32_t*)&l1);
            }
            #pragma unroll
            for (int l = 0; l < 4; l++) {
                int u  = tid + l * 256;
                int n  = u >> 3;
                int ch = (u & 7) * 16;
                uint32_t dst = (uint32_t)n * ROWB + (uint32_t)ch;
                const char* srch = (const char*)&d_Wt_hi[n * FIN + kt] + ch;
                const char* srcl = (const char*)&d_Wt_lo[n * FIN + kt] + ch;
                *(uint4*)(smem + BH_OFF + dst) = *(const uint4*)srch;
                *(uint4*)(smem + BL_OFF + dst) = *(const uint4*)srcl;
            }
            __syncthreads();

            #pragma unroll
            for (int ks = 0; ks < 4; ks++) {
                const uint32_t colB = (uint32_t)ks * 32 + (uint32_t)(lane >> 4) * 16;
                uint32_t a_hi[4], a_lo[4];
                {
                    uint32_t roff = (uint32_t)(mb0 + (lane & 15)) * ROWB + colB;
                    ldm_x4(a_hi[0], a_hi[1], a_hi[2], a_hi[3], sb + AH_OFF + roff);
                    ldm_x4(a_lo[0], a_lo[1], a_lo[2], a_lo[3], sb + AL_OFF + roff);
                }
                #pragma unroll
                for (int g = 0; g < 4; g++) {
                    uint32_t roff = (uint32_t)(nb + g * 16 + (lane & 15)) * ROWB + colB;
                    uint32_t b0, b1, b2, b3;
                    ldm_x4(b0, b1, b2, b3, sb + BH_OFF + roff);
                    mma_bf16(acc[g * 2],     a_hi, b0, b2);
                    mma_bf16(acc[g * 2 + 1], a_hi, b1, b3);
                    mma_bf16(acc[g * 2],     a_lo, b0, b2);
                    mma_bf16(acc[g * 2 + 1], a_lo, b1, b3);
                    ldm_x4(b0, b1, b2, b3, sb + BL_OFF + roff);
                    mma_bf16(acc[g * 2],     a_hi, b0, b2);
                    mma_bf16(acc[g * 2 + 1], a_hi, b1, b3);
                }
            }
        }

        // epilogue: store Wh only
        const int r0 = mb0 + (lane >> 2);
        const int r1 = r0 + 8;
        #pragma unroll
        for (int nt = 0; nt < 8; nt++) {
            const int col = nb + nt * 8 + (lane & 3) * 2;
            *(float2*)&d_Wh[(size_t)(rowBase + r0) * D + col] = make_float2(acc[nt][0], acc[nt][1]);
            *(float2*)&d_Wh[(size_t)(rowBase + r1) * D + col] = make_float2(acc[nt][2], acc[nt][3]);
        }
        return;
    }

    // ===================== SORT (16 blocks, 256 thr, 8 elem/thread) ============
    {
        const int s = blockIdx.x - 256;
        const int role = s & 1, b = s >> 1;
        const int t = tid;
        const int lane = t & 31, warp = t >> 5;
        float* sk = (float*)smem;              // 2048 floats
        int*   sx = (int*)(smem + 8192);       // 2048 ints
        float* wt = (float*)(smem + 16384);    // 16 floats (warp totals e,a)

        const float* src = (role == 0 ? d_s1 : d_s2) + b * NTOK;
        float key[8];
        int   idx[8];
        *(float4*)&key[0] = *(const float4*)&src[8 * t];
        *(float4*)&key[4] = *(const float4*)&src[8 * t + 4];
        #pragma unroll
        for (int e = 0; e < 8; e++) idx[e] = 8 * t + e;

        // k=2: pairs (0,1)(2,3)(4,5)(6,7), up = ((e&2)==0)
        cmpswap(key[0], idx[0], key[1], idx[1], true);
        cmpswap(key[2], idx[2], key[3], idx[3], false);
        cmpswap(key[4], idx[4], key[5], idx[5], true);
        cmpswap(key[6], idx[6], key[7], idx[7], false);
        // k=4: up = ((e&4)==0)
        #pragma unroll
        for (int j = 2; j >= 1; j >>= 1)
            #pragma unroll
            for (int e = 0; e < 8; e++)
                if ((e & j) == 0) cmpswap(key[e], idx[e], key[e + j], idx[e + j], (e & 4) == 0);
        // k=8: up = ((t&1)==0)
        {
            bool up8 = ((t & 1) == 0);
            #pragma unroll
            for (int j = 4; j >= 1; j >>= 1)
                #pragma unroll
                for (int e = 0; e < 8; e++)
                    if ((e & j) == 0) cmpswap(key[e], idx[e], key[e + j], idx[e + j], up8);
        }

        // k = 16..256: shuffle js (m = j>>3 in 1..16) + in-thread tail
        #pragma unroll 1
        for (int k = 16; k <= 256; k <<= 1) {
            const bool up = ((t & (k >> 3)) == 0);
            for (int j = k >> 1; j >= 8; j >>= 1)
                shuffle_pass(key, idx, j >> 3, up);
            tail_pass(key, idx, up);
        }

        // k = 512..2048: smem js (>=256), then shuffle, then tail
        #pragma unroll 1
        for (int k = 512; k <= 2048; k <<= 1) {
            const bool up = ((t & (k >> 3)) == 0);
            *(float4*)&sk[8 * t]     = *(float4*)&key[0];
            *(float4*)&sk[8 * t + 4] = *(float4*)&key[4];
            *(int4*)&sx[8 * t]       = *(int4*)&idx[0];
            *(int4*)&sx[8 * t + 4]   = *(int4*)&idx[4];
            __syncthreads();
            for (int j = k >> 1; j >= 256; j >>= 1) {
                if ((t & (j >> 3)) == 0) {
                    #pragma unroll
                    for (int e = 0; e < 8; e++) {
                        int i = 8 * t + e, p = i + j;
                        float A = sk[i], Bv = sk[p];
                        if ((A > Bv) == up) {
                            sk[i] = Bv; sk[p] = A;
                            int tI = sx[i]; sx[i] = sx[p]; sx[p] = tI;
                        }
                    }
                }
                __syncthreads();
            }
            *(float4*)&key[0] = *(float4*)&sk[8 * t];
            *(float4*)&key[4] = *(float4*)&sk[8 * t + 4];
            *(int4*)&idx[0]   = *(int4*)&sx[8 * t];
            *(int4*)&idx[4]   = *(int4*)&sx[8 * t + 4];
            for (int j = 128; j >= 8; j >>= 1)
                shuffle_pass(key, idx, j >> 3, up);
            tail_pass(key, idx, up);
        }

        if (role == 1) {
            *(float4*)&d_s2s[b * NTOK + 8 * t]     = *(float4*)&key[0];
            *(float4*)&d_s2s[b * NTOK + 8 * t + 4] = *(float4*)&key[4];
            *(int4*)&d_perm[b * NTOK + 8 * t]      = *(int4*)&idx[0];
            *(int4*)&d_perm[b * NTOK + 8 * t + 4]  = *(int4*)&idx[4];
            return;
        }

        // role 0: exps + inclusive prefix scans
        float pe_[8], pa_[8];
        float se = 0.f, sa = 0.f;
        #pragma unroll
        for (int e = 0; e < 8; e++) {
            se += expf(key[e]);          pe_[e] = se;
            sa += expf(ALPHA * key[e]);  pa_[e] = sa;
        }
        float we = se, wa = sa;
        #pragma unroll
        for (int o = 1; o < 32; o <<= 1) {
            float te = __shfl_up_sync(0xffffffffu, we, o);
            float ta = __shfl_up_sync(0xffffffffu, wa, o);
            if (lane >= o) { we += te; wa += ta; }
        }
        if (lane == 31) { wt[warp] = we; wt[8 + warp] = wa; }
        __syncthreads();
        float offE = 0.f, offA = 0.f;
        for (int w = 0; w < warp; w++) { offE += wt[w]; offA += wt[8 + w]; }
        const float baseE = offE + (we - se);
        const float baseA = offA + (wa - sa);
        #pragma unroll
        for (int e = 0; e < 8; e++) { pe_[e] += baseE; pa_[e] += baseA; }

        *(float4*)&d_ss1[b * NTOK + 8 * t]     = *(float4*)&key[0];
        *(float4*)&d_ss1[b * NTOK + 8 * t + 4] = *(float4*)&key[4];
        *(float4*)&d_pe[b * NTOK + 8 * t]      = *(float4*)&pe_[0];
        *(float4*)&d_pe[b * NTOK + 8 * t + 4]  = *(float4*)&pe_[4];
        *(float4*)&d_pa[b * NTOK + 8 * t]      = *(float4*)&pa_[0];
        *(float4*)&d_pa[b * NTOK + 8 * t + 4]  = *(float4*)&pa_[4];
    }
}

// ------- K2b: fully smem-staged searches + prefix lookups ----------------------
__global__ void __launch_bounds__(256) k_gfill()
{
    __shared__ float sarr[NTOK];
    __shared__ float spe[NTOK];
    __shared__ float spa[NTOK];

    const int b = blockIdx.y, tid = threadIdx.x;
    const int idx = blockIdx.x * 256 + tid;

    if (blockIdx.z == 0) {
        #pragma unroll
        for (int l = 0; l < 2; l++) {
            int f4 = tid + l * 256;
            *(float4*)&sarr[f4 * 4] = *(const float4*)&d_ss1[b * NTOK + f4 * 4];
            *(float4*)&spe[f4 * 4]  = *(const float4*)&d_pe[b * NTOK + f4 * 4];
            *(float4*)&spa[f4 * 4]  = *(const float4*)&d_pa[b * NTOK + f4 * 4];
        }
        __syncthreads();

        float s2v = __ldg(&d_s2s[b * NTOK + idx]);
        float keyv = -s2v;
        int lo = 0;
        #pragma unroll
        for (int step = 1024; step >= 1; step >>= 1) {
            int probe = lo + step - 1;
            if (probe < NTOK && sarr[probe] < keyv) lo += step;
        }
        const float totE = spe[NTOK - 1];
        float preE = lo > 0 ? spe[lo - 1] : 0.f;
        float preA = lo > 0 ? spa[lo - 1] : 0.f;
        float e2  = expf(s2v);
        float ea2 = expf(ALPHA * s2v);
        float inv = 1.f / (e2 * (totE - preE) + ea2 * preA);
        d_g1[b * NTOK + idx] = e2  * inv;
        d_g2[b * NTOK + idx] = ea2 * inv;
    } else {
        #pragma unroll
        for (int l = 0; l < 2; l++) {
            int f4 = tid + l * 256;
            *(float4*)&sarr[f4 * 4] = *(const float4*)&d_s2s[b * NTOK + f4 * 4];
        }
        __syncthreads();

        float s1v = __ldg(&d_s1[b * NTOK + idx]);
        float keyv = -s1v;
        int lo = 0;
        #pragma unroll
        for (int step = 1024; step >= 1; step >>= 1) {
            int probe = lo + step - 1;
            if (probe < NTOK && sarr[probe] < keyv) lo += step;
        }
        d_tq[b * NTOK + idx] = lo;
        d_e1[b * NTOK + idx] = expf(s1v);
        d_e2[b * NTOK + idx] = expf(ALPHA * s1v);
    }
}

// ------- K3: prefix sums, 2 dims/thread, STG.128 stores, 2 chunks/block --------
__global__ void __launch_bounds__(128) k_scan()
{
    __shared__ int   sp[2][CHUNK];
    __shared__ float sg1[2][CHUNK], sg2[2][CHUNK];

    const int b    = blockIdx.y;
    const int half = threadIdx.x >> 6;
    const int t64  = threadIdx.x & 63;
    const int c    = blockIdx.x * 2 + half;
    const int base = b * NTOK + c * CHUNK;
    const int d0   = t64 * 2;

    if (t64 < CHUNK) {
        sp [half][t64] = d_perm[base + t64];
        sg1[half][t64] = d_g1[base + t64];
        sg2[half][t64] = d_g2[base + t64];
    }
    __syncthreads();

    float2 w[CHUNK];
    #pragma unroll
    for (int r = 0; r < CHUNK; r++)
        w[r] = *(const float2*)&d_Wh[((size_t)b * NTOK + sp[half][r]) * D + d0];

    float s1a = 0.f, s2a = 0.f, s1b = 0.f, s2b = 0.f;
    #pragma unroll
    for (int r = 0; r < CHUNK; r++) {
        float g1 = sg1[half][r], g2 = sg2[half][r];
        s1a += g1 * w[r].x;  s2a += g2 * w[r].x;
        s1b += g1 * w[r].y;  s2b += g2 * w[r].y;
        *(float4*)&d_loc12[((size_t)(base + r) * D + d0) * 2] = make_float4(s1a, s2a, s1b, s2b);
    }
    const int cb = (b * NCHUNK + c) * D + d0;
    *(float2*)&d_ct1[cb] = make_float2(s1a, s1b);
    *(float2*)&d_ct2[cb] = make_float2(s2a, s2b);
}

// ------- K4: two-phase exclusive scan of 128 chunk totals ---------------------
__global__ void __launch_bounds__(1024) k_coff()
{
    __shared__ float part1[8][D];
    __shared__ float part2[8][D];

    const int b = blockIdx.x;
    const int d = threadIdx.x & 127;
    const int g = threadIdx.x >> 7;

    float v1[16], v2[16];
    #pragma unroll
    for (int r = 0; r < 16; r++) {
        int c = g * 16 + r;
        v1[r] = d_ct1[(b * NCHUNK + c) * D + d];
        v2[r] = d_ct2[(b * NCHUNK + c) * D + d];
    }
    float run1 = 0.f, run2 = 0.f;
    #pragma unroll
    for (int r = 0; r < 16; r++) {
        float t1 = v1[r]; v1[r] = run1; run1 += t1;
        float t2 = v2[r]; v2[r] = run2; run2 += t2;
    }
    part1[g][d] = run1;
    part2[g][d] = run2;
    __syncthreads();

    if (g == 0) {
        float r1 = 0.f, r2 = 0.f;
        #pragma unroll
        for (int gg = 0; gg < 8; gg++) {
            float t1 = part1[gg][d]; part1[gg][d] = r1; r1 += t1;
            float t2 = part2[gg][d]; part2[gg][d] = r2; r2 += t2;
        }
        d_tot1[b * D + d] = r1;
    }
    __syncthreads();

    const float o1 = part1[g][d];
    const float o2 = part2[g][d];
    #pragma unroll
    for (int r = 0; r < 16; r++) {
        int c = g * 16 + r;
        *(float2*)&d_cp12[((size_t)(b * NCHUNK + c) * D + d) * 2] = make_float2(o1 + v1[r], o2 + v2[r]);
    }
}

// ------- K5: wide gather + ELU --------------------------------------------------
__global__ void __launch_bounds__(256) k_out(float* __restrict__ out)
{
    const int gq   = blockIdx.x * 8 + (threadIdx.x >> 5);
    const int lane = threadIdx.x & 31;
    const int b    = gq >> 11;
    const int d4   = lane * 4;

    const int   t  = d_tq[gq];
    const float e1 = d_e1[gq];
    const float e2 = d_e2[gq];

    float4 tot = *(const float4*)&d_tot1[b * D + d4];
    float4 P1 = {0.f, 0.f, 0.f, 0.f};
    float4 P2 = {0.f, 0.f, 0.f, 0.f};

    if (t > 0) {
        int k = t - 1;
        int c = k >> 4;
        size_t kb = ((size_t)(b * NTOK + k) * D + d4) * 2;
        size_t cb = ((size_t)(b * NCHUNK + c) * D + d4) * 2;
        float4 u0 = *(const float4*)&d_loc12[kb];
        float4 u1 = *(const float4*)&d_loc12[kb + 4];
        float4 q0 = *(const float4*)&d_cp12[cb];
        float4 q1 = *(const float4*)&d_cp12[cb + 4];
        P1.x = u0.x + q0.x; P2.x = u0.y + q0.y;
        P1.y = u0.z + q0.z; P2.y = u0.w + q0.w;
        P1.z = u1.x + q1.x; P2.z = u1.y + q1.y;
        P1.w = u1.z + q1.z; P2.w = u1.w + q1.w;
    }

    float4 v;
    v.x = e1 * (tot.x - P1.x) + e2 * P2.x;
    v.y = e1 * (tot.y - P1.y) + e2 * P2.y;
    v.z = e1 * (tot.z - P1.z) + e2 * P2.z;
    v.w = e1 * (tot.w - P1.w) + e2 * P2.w;
    v.x = v.x > 0.f ? v.x : expm1f(v.x);
    v.y = v.y > 0.f ? v.y : expm1f(v.y);
    v.z = v.z > 0.f ? v.z : expm1f(v.z);
    v.w = v.w > 0.f ? v.w : expm1f(v.w);

    *(float4*)&out[(size_t)gq * D + d4] = v;
}

// -----------------------------------------------------------------------------
extern "C" void kernel_launch(void* const* d_in, const int* in_sizes, int n_in,
                              void* d_out, int out_size)
{
    const float* h = (const float*)d_in[0];   // [8,2048,256]
    const float* W = (const float*)d_in[1];   // [256,128]
    const float* a = (const float*)d_in[2];   // [256,1]
    float* out = (float*)d_out;               // [8,2048,128]

    cudaFuncSetAttribute(k_mega, cudaFuncAttributeMaxDynamicSharedMemorySize, SM_TOT);

    k_u    <<<129, 256>>>(W, a);
    k_su   <<<(B * NTOK) / 8, 256>>>(h);
    k_mega <<<256 + 2 * B, 256, SM_TOT>>>(h);
    k_gfill<<<dim3(8, B, 2), 256>>>();
    k_scan <<<dim3(NCHUNK / 2, B), 128>>>();
    k_coff <<<B, 1024>>>();
    k_out  <<<(B * NTOK) / 8, 256>>>(out);
}